// round 5
// baseline (speedup 1.0000x reference)
#include <cuda_runtime.h>

#define B_   16
#define N_   2048
#define F_   128
#define HID_ 32
#define FC_  512
#define C_   10

#define BM 256
#define BK 32
#define AS_STRIDE 260   // BM + 4 pad (multiple of 4 for LDS.128 alignment, conflict-free)

// Scratch (no cudaMalloc allowed)
__device__ float g_XW[B_ * N_ * HID_];     // X @ W1  [B,N,HID]  (4 MB)
__device__ float g_part[B_ * 8 * HID_];    // per-block relu column sums

__device__ __forceinline__ unsigned long long ffma2(unsigned long long a,
                                                    unsigned long long b,
                                                    unsigned long long c) {
    unsigned long long d;
    asm("fma.rn.f32x2 %0, %1, %2, %3;" : "=l"(d) : "l"(a), "l"(b), "l"(c));
    return d;
}
__device__ __forceinline__ unsigned long long dup2(float x) {
    unsigned long long d;
    asm("mov.b64 %0, {%1, %1};" : "=l"(d) : "r"(__float_as_uint(x)));
    return d;
}

// ---------------------------------------------------------------------------
// Kernel 1: XW[b,m,h] = sum_f X[b,m,f] * W1[f,h]
// grid (N/8, B), 256 threads: 8 rows x 32 cols per block, W1 cached in smem.
// ---------------------------------------------------------------------------
__global__ __launch_bounds__(256) void xw_kernel(const float* __restrict__ X,
                                                 const float* __restrict__ W1) {
    __shared__ __align__(16) float W1s[F_ * HID_];
    const int tid = threadIdx.x;
    const int b = blockIdx.y;

    for (int i = tid; i < (F_ * HID_) / 4; i += 256)
        reinterpret_cast<float4*>(W1s)[i] = reinterpret_cast<const float4*>(W1)[i];
    __syncthreads();

    const int mloc = tid >> 5;
    const int h = tid & 31;
    const int m = blockIdx.x * 8 + mloc;
    const float* xrow = X + ((size_t)b * N_ + m) * F_;

    float acc = 0.f;
#pragma unroll
    for (int f4 = 0; f4 < F_ / 4; f4++) {
        float4 xv = reinterpret_cast<const float4*>(xrow)[f4];
        acc = fmaf(xv.x, W1s[(f4 * 4 + 0) * HID_ + h], acc);
        acc = fmaf(xv.y, W1s[(f4 * 4 + 1) * HID_ + h], acc);
        acc = fmaf(xv.z, W1s[(f4 * 4 + 2) * HID_ + h], acc);
        acc = fmaf(xv.w, W1s[(f4 * 4 + 3) * HID_ + h], acc);
    }
    g_XW[((size_t)b * N_ + m) * HID_ + h] = acc;
}

// ---------------------------------------------------------------------------
// Kernel 2: Y = A @ XW (M=2048,K=2048,N=32 per batch), relu(Y + b1),
// deterministic column-sum over this block's 256 rows -> g_part[b][mb][32].
// grid (N/BM, B), 256 threads (8 warps). Warp: 8 lane-rows x 4 lane-cols;
// lane tile: 4 rows x 8 cols = 16 f32x2 accumulators.
// ---------------------------------------------------------------------------
__global__ __launch_bounds__(256) void gemm_kernel(const float* __restrict__ A,
                                                   const float* __restrict__ b1) {
    __shared__ __align__(16) float As[BK * AS_STRIDE];  // transposed: As[k][row]
    __shared__ __align__(16) float XWs[BK * HID_];
    __shared__ float red[8 * HID_];

    const int tid = threadIdx.x;
    const int b = blockIdx.y;
    const int mb = blockIdx.x;

    const int w = tid >> 5;
    const int lane = tid & 31;
    const int lc = lane & 3;       // lane-col group
    const int lr = lane >> 2;      // lane-row group
    const int r0 = w * 32 + lr * 4;     // local rows r0..r0+3
    const int cbase = lc * 8;           // cols cbase..cbase+7

    unsigned long long acc[4][4];
#pragma unroll
    for (int j = 0; j < 4; j++)
#pragma unroll
        for (int p = 0; p < 4; p++) acc[j][p] = 0ull;

    const float* Ab  = A    + ((size_t)b * N_ + (size_t)mb * BM) * N_;
    const float* XWb = g_XW + (size_t)b * N_ * HID_;

    const int rl = tid >> 3;   // 0..31 (load row within pass)
    const int kp = tid & 7;    // 0..7  (load k-quad)

    for (int k0 = 0; k0 < N_; k0 += BK) {
        // --- A tile: coalesced float4 global reads, transposed scalar STS ---
#pragma unroll
        for (int p = 0; p < 8; p++) {
            int row = rl + p * 32;
            float4 av = *reinterpret_cast<const float4*>(Ab + (size_t)row * N_ + k0 + kp * 4);
            As[(kp * 4 + 0) * AS_STRIDE + row] = av.x;
            As[(kp * 4 + 1) * AS_STRIDE + row] = av.y;
            As[(kp * 4 + 2) * AS_STRIDE + row] = av.z;
            As[(kp * 4 + 3) * AS_STRIDE + row] = av.w;
        }
        // --- XW tile: 1024 floats, one float4 per thread ---
        {
            int kk = tid >> 3;
            int cc = (tid & 7) * 4;
            *reinterpret_cast<float4*>(&XWs[kk * HID_ + cc]) =
                *reinterpret_cast<const float4*>(XWb + (size_t)(k0 + kk) * HID_ + cc);
        }
        __syncthreads();

#pragma unroll 8
        for (int k = 0; k < BK; k++) {
            float4 a4 = *reinterpret_cast<const float4*>(&As[k * AS_STRIDE + r0]);
            unsigned long long ad[4];
            ad[0] = dup2(a4.x); ad[1] = dup2(a4.y);
            ad[2] = dup2(a4.z); ad[3] = dup2(a4.w);
            unsigned long long bx[4];
#pragma unroll
            for (int p = 0; p < 4; p++)
                bx[p] = *reinterpret_cast<const unsigned long long*>(&XWs[k * HID_ + cbase + 2 * p]);
#pragma unroll
            for (int j = 0; j < 4; j++)
#pragma unroll
                for (int p = 0; p < 4; p++)
                    acc[j][p] = ffma2(ad[j], bx[p], acc[j][p]);
        }
        __syncthreads();
    }

    // Epilogue: relu(Y + b1), sum over the 4 local rows
    float2 b1p[4];
#pragma unroll
    for (int p = 0; p < 4; p++)
        b1p[p] = *reinterpret_cast<const float2*>(b1 + cbase + 2 * p);

    float2 csum[4];
#pragma unroll
    for (int p = 0; p < 4; p++) csum[p] = make_float2(0.f, 0.f);
#pragma unroll
    for (int j = 0; j < 4; j++) {
#pragma unroll
        for (int p = 0; p < 4; p++) {
            float lo = __uint_as_float((unsigned)(acc[j][p] & 0xffffffffull));
            float hi = __uint_as_float((unsigned)(acc[j][p] >> 32));
            lo = fmaxf(lo + b1p[p].x, 0.f);
            hi = fmaxf(hi + b1p[p].y, 0.f);
            csum[p].x += lo;
            csum[p].y += hi;
        }
    }
    // Butterfly reduce across the 8 lane-rows (lr bits = lane bits 2..4)
#pragma unroll
    for (int p = 0; p < 4; p++) {
#pragma unroll
        for (int off = 16; off >= 4; off >>= 1) {
            csum[p].x += __shfl_xor_sync(0xffffffffu, csum[p].x, off);
            csum[p].y += __shfl_xor_sync(0xffffffffu, csum[p].y, off);
        }
    }
    if (lr == 0) {
#pragma unroll
        for (int p = 0; p < 4; p++) {
            red[w * HID_ + cbase + 2 * p + 0] = csum[p].x;
            red[w * HID_ + cbase + 2 * p + 1] = csum[p].y;
        }
    }
    __syncthreads();
    if (tid < HID_) {
        float s = 0.f;
#pragma unroll
        for (int ww = 0; ww < 8; ww++) s += red[ww * HID_ + tid];
        g_part[((size_t)b * 8 + mb) * HID_ + tid] = s;
    }
}

// ---------------------------------------------------------------------------
// Kernel 3: Xp = sum(partials); h = relu(Xp@Wd + bd); out = softmax(h@Wc + bc)
// grid B, 512 threads (one per FC unit).
// ---------------------------------------------------------------------------
__global__ __launch_bounds__(512) void head_kernel(const float* __restrict__ Wd,
                                                   const float* __restrict__ bd,
                                                   const float* __restrict__ Wc,
                                                   const float* __restrict__ bc,
                                                   float* __restrict__ out) {
    __shared__ float xp[HID_];
    __shared__ float hbuf[FC_];
    __shared__ float logits[C_];
    const int b = blockIdx.x;
    const int tid = threadIdx.x;

    if (tid < HID_) {
        float s = 0.f;
#pragma unroll
        for (int mb = 0; mb < 8; mb++)
            s += g_part[((size_t)b * 8 + mb) * HID_ + tid];
        xp[tid] = s;
    }
    __syncthreads();

    {
        float acc = bd[tid];
#pragma unroll
        for (int h = 0; h < HID_; h++)
            acc = fmaf(xp[h], Wd[h * FC_ + tid], acc);
        hbuf[tid] = fmaxf(acc, 0.f);
    }
    __syncthreads();

    if (tid < C_) {
        float acc = bc[tid];
        for (int f = 0; f < FC_; f++)
            acc = fmaf(hbuf[f], Wc[f * C_ + tid], acc);
        logits[tid] = acc;
    }
    __syncthreads();

    if (tid == 0) {
        float mx = logits[0];
#pragma unroll
        for (int c = 1; c < C_; c++) mx = fmaxf(mx, logits[c]);
        float e[C_];
        float sum = 0.f;
#pragma unroll
        for (int c = 0; c < C_; c++) { e[c] = expf(logits[c] - mx); sum += e[c]; }
        float inv = 1.f / sum;
#pragma unroll
        for (int c = 0; c < C_; c++) out[b * C_ + c] = e[c] * inv;
    }
}

// ---------------------------------------------------------------------------
extern "C" void kernel_launch(void* const* d_in, const int* in_sizes, int n_in,
                              void* d_out, int out_size) {
    const float* filtre = (const float*)d_in[0];
    const float* X      = (const float*)d_in[1];
    // d_in[2] node_indicator: unused by the reference math
    const float* W1     = (const float*)d_in[3];
    const float* b1     = (const float*)d_in[4];
    // d_in[5] Ws: dead (softmax over size-1 cluster axis == 1)
    const float* Wd     = (const float*)d_in[6];
    const float* bd     = (const float*)d_in[7];
    const float* Wc     = (const float*)d_in[8];
    const float* bc     = (const float*)d_in[9];
    float* out = (float*)d_out;

    xw_kernel<<<dim3(N_ / 8, B_), 256>>>(X, W1);
    gemm_kernel<<<dim3(N_ / BM, B_), 256>>>(filtre, b1);
    head_kernel<<<B_, FC_>>>(Wd, bd, Wc, bc, out);
}

// round 7
// speedup vs baseline: 2.5539x; 2.5539x over previous
#include <cuda_runtime.h>

#define B_   16
#define N_   2048
#define F_   128
#define HID_ 32
#define FC_  512
#define C_   10

#define BM   128          // rows per gemm block
#define BK   32           // k-tile
#define NKT  (N_ / BK)    // 64 k-tiles
#define ASTR 36           // A smem stride (pad: bank = 4*row+ k, conflict-free frags)
#define BSTR 40           // B smem stride (pad: bank = 8*k + n, conflict-free frags)
#define MB_  (N_ / BM)    // 16 m-blocks per batch

// Scratch (no cudaMalloc allowed)
__device__ float g_XW[B_ * N_ * HID_];        // X @ W1  [B,N,HID]
__device__ float g_part[B_ * MB_ * HID_];     // per-block relu column sums

// ---------------- helpers ----------------
__device__ __forceinline__ unsigned long long ffma2(unsigned long long a,
                                                    unsigned long long b,
                                                    unsigned long long c) {
    unsigned long long d;
    asm("fma.rn.f32x2 %0, %1, %2, %3;" : "=l"(d) : "l"(a), "l"(b), "l"(c));
    return d;
}
__device__ __forceinline__ unsigned long long dup2(float x) {
    unsigned long long d;
    asm("mov.b64 %0, {%1, %1};" : "=l"(d) : "r"(__float_as_uint(x)));
    return d;
}
__device__ __forceinline__ void cp16(float* dst_smem, const float* src) {
    unsigned s = (unsigned)__cvta_generic_to_shared(dst_smem);
    asm volatile("cp.async.cg.shared.global [%0], [%1], 16;" :: "r"(s), "l"(src));
}
__device__ __forceinline__ void cp_commit() { asm volatile("cp.async.commit_group;"); }
__device__ __forceinline__ void cp_wait1()  { asm volatile("cp.async.wait_group 1;"); }
__device__ __forceinline__ void cp_wait0()  { asm volatile("cp.async.wait_group 0;"); }

__device__ __forceinline__ void mma_tf32(float c[4], float a0, float a1, float a2, float a3,
                                         float b0, float b1) {
    asm volatile(
        "mma.sync.aligned.m16n8k8.row.col.f32.tf32.tf32.f32 "
        "{%0,%1,%2,%3}, {%4,%5,%6,%7}, {%8,%9}, {%0,%1,%2,%3};"
        : "+f"(c[0]), "+f"(c[1]), "+f"(c[2]), "+f"(c[3])
        : "r"(__float_as_uint(a0)), "r"(__float_as_uint(a1)),
          "r"(__float_as_uint(a2)), "r"(__float_as_uint(a3)),
          "r"(__float_as_uint(b0)), "r"(__float_as_uint(b1)));
}

// ---------------------------------------------------------------------------
// Kernel 1: XW = X @ W1.  Block: 64 rows, 256 threads, smem-tiled, f32x2.
// grid (N/64, B)
// ---------------------------------------------------------------------------
#define XROWS 64
#define XSTR  132   // pad so broadcast LDS of Xs[row][f] is conflict-free (bank=4row+f)
__global__ __launch_bounds__(256) void xw_kernel(const float* __restrict__ X,
                                                 const float* __restrict__ W1) {
    __shared__ __align__(16) float Xs[XROWS * XSTR];
    __shared__ __align__(16) float W1s[F_ * HID_];
    const int tid = threadIdx.x;
    const int b = blockIdx.y;
    const int m0 = blockIdx.x * XROWS;
    const float* Xb = X + ((size_t)b * N_ + m0) * F_;

#pragma unroll
    for (int i = 0; i < 4; i++)
        reinterpret_cast<float4*>(W1s)[tid + 256 * i] =
            reinterpret_cast<const float4*>(W1)[tid + 256 * i];
#pragma unroll
    for (int i = 0; i < 8; i++) {
        int c = tid + 256 * i;          // float4 index; 32 float4 per row
        int row = c >> 5, q = c & 31;
        *reinterpret_cast<float4*>(&Xs[row * XSTR + q * 4]) =
            reinterpret_cast<const float4*>(Xb)[c];
    }
    __syncthreads();

    const int row = tid >> 2;           // 64 rows
    const int cg = tid & 3;             // cols cg*8 .. cg*8+7
    unsigned long long acc2[4] = {0ull, 0ull, 0ull, 0ull};

#pragma unroll 16
    for (int f = 0; f < F_; f++) {
        unsigned long long xd = dup2(Xs[row * XSTR + f]);
#pragma unroll
        for (int p = 0; p < 4; p++)
            acc2[p] = ffma2(xd,
                *reinterpret_cast<const unsigned long long*>(&W1s[f * HID_ + cg * 8 + 2 * p]),
                acc2[p]);
    }

    float* out = g_XW + ((size_t)b * N_ + m0 + row) * HID_ + cg * 8;
#pragma unroll
    for (int p = 0; p < 4; p++)
        *reinterpret_cast<unsigned long long*>(&out[2 * p]) = acc2[p];
}

// ---------------------------------------------------------------------------
// Kernel 2: Y = A @ XW per batch (M=2048,K=2048,N=32), relu(Y+b1),
// deterministic column-sum -> g_part[b][mb][32].
// tf32 mma.sync m16n8k8, cp.async double-buffered.
// grid (MB_, B), 256 threads (8 warps, 1 m16-tile each, 4 n8-tiles).
// ---------------------------------------------------------------------------
__global__ __launch_bounds__(256) void gemm_kernel(const float* __restrict__ A,
                                                   const float* __restrict__ b1) {
    __shared__ __align__(16) float As[2][BM * ASTR];
    __shared__ __align__(16) float Bs[2][BK * BSTR];
    __shared__ float red[8 * HID_];

    const int tid = threadIdx.x;
    const int b = blockIdx.y;
    const int mb = blockIdx.x;
    const int w = tid >> 5;
    const int lane = tid & 31;
    const int g = lane >> 2;      // group row 0..7
    const int t = lane & 3;       // thread-in-group 0..3

    const float* Ab  = A    + ((size_t)b * N_ + (size_t)mb * BM) * N_;
    const float* XWb = g_XW + (size_t)b * N_ * HID_;

    float acc[4][4];
#pragma unroll
    for (int nt = 0; nt < 4; nt++)
#pragma unroll
        for (int i = 0; i < 4; i++) acc[nt][i] = 0.f;

    // staging: A tile 128x32 (1024 16B chunks, 4/thread), B tile 32x32 (1/thread)
    const int ar = tid >> 3;          // base row for A chunks (c>>3 pattern below)
    const int aq = tid & 7;
    (void)ar; (void)aq;

#define STAGE(kt, p)                                                            \
    do {                                                                        \
        int k0s = (kt) * BK;                                                    \
        _Pragma("unroll")                                                       \
        for (int i = 0; i < 4; i++) {                                           \
            int c = tid + i * 256;                                              \
            int row = c >> 3, kq = c & 7;                                       \
            cp16(&As[p][row * ASTR + kq * 4],                                   \
                 Ab + (size_t)row * N_ + k0s + kq * 4);                         \
        }                                                                       \
        {                                                                       \
            int kk = tid >> 3, j = tid & 7;                                     \
            cp16(&Bs[p][kk * BSTR + j * 4],                                     \
                 XWb + (size_t)(k0s + kk) * HID_ + j * 4);                      \
        }                                                                       \
        cp_commit();                                                            \
    } while (0)

    STAGE(0, 0);

    for (int kt = 0; kt < NKT; kt++) {
        const int p = kt & 1;
        if (kt + 1 < NKT) { STAGE(kt + 1, p ^ 1); cp_wait1(); }
        else               cp_wait0();
        __syncthreads();

        const float* Asp = As[p];
        const float* Bsp = Bs[p];
#pragma unroll
        for (int kc = 0; kc < 4; kc++) {
            const int kb = kc * 8;
            float a0 = Asp[(w * 16 + g)     * ASTR + kb + t];
            float a1 = Asp[(w * 16 + g + 8) * ASTR + kb + t];
            float a2 = Asp[(w * 16 + g)     * ASTR + kb + t + 4];
            float a3 = Asp[(w * 16 + g + 8) * ASTR + kb + t + 4];
#pragma unroll
            for (int nt = 0; nt < 4; nt++) {
                float bb0 = Bsp[(kb + t)     * BSTR + nt * 8 + g];
                float bb1 = Bsp[(kb + t + 4) * BSTR + nt * 8 + g];
                mma_tf32(acc[nt], a0, a1, a2, a3, bb0, bb1);
            }
        }
        __syncthreads();
    }

    // Epilogue: +b1, relu, sum over this block's 128 rows (deterministic).
    // Lane holds cols {2t, 2t+1} per n-tile at rows g and g+8.
    float2 csum[4];
#pragma unroll
    for (int nt = 0; nt < 4; nt++) {
        float2 bb = *reinterpret_cast<const float2*>(b1 + nt * 8 + 2 * t);
        float v0 = fmaxf(acc[nt][0] + bb.x, 0.f) + fmaxf(acc[nt][2] + bb.x, 0.f);
        float v1 = fmaxf(acc[nt][1] + bb.y, 0.f) + fmaxf(acc[nt][3] + bb.y, 0.f);
        csum[nt] = make_float2(v0, v1);
    }
    // reduce over the 8 group-rows (lane bits 2..4)
#pragma unroll
    for (int nt = 0; nt < 4; nt++) {
#pragma unroll
        for (int off = 16; off >= 4; off >>= 1) {
            csum[nt].x += __shfl_xor_sync(0xffffffffu, csum[nt].x, off);
            csum[nt].y += __shfl_xor_sync(0xffffffffu, csum[nt].y, off);
        }
    }
    if (g == 0) {
#pragma unroll
        for (int nt = 0; nt < 4; nt++) {
            red[w * HID_ + nt * 8 + 2 * t + 0] = csum[nt].x;
            red[w * HID_ + nt * 8 + 2 * t + 1] = csum[nt].y;
        }
    }
    __syncthreads();
    if (tid < HID_) {
        float s = 0.f;
#pragma unroll
        for (int ww = 0; ww < 8; ww++) s += red[ww * HID_ + tid];
        g_part[((size_t)b * MB_ + mb) * HID_ + tid] = s;
    }
}

// ---------------------------------------------------------------------------
// Kernel 3: Xp = sum(partials); h = relu(Xp@Wd+bd); out = softmax(h@Wc+bc)
// ---------------------------------------------------------------------------
__global__ __launch_bounds__(512) void head_kernel(const float* __restrict__ Wd,
                                                   const float* __restrict__ bd,
                                                   const float* __restrict__ Wc,
                                                   const float* __restrict__ bc,
                                                   float* __restrict__ out) {
    __shared__ float xp[HID_];
    __shared__ float hbuf[FC_];
    __shared__ float logits[C_];
    const int b = blockIdx.x;
    const int tid = threadIdx.x;

    if (tid < HID_) {
        float s = 0.f;
#pragma unroll
        for (int mb = 0; mb < MB_; mb++)
            s += g_part[((size_t)b * MB_ + mb) * HID_ + tid];
        xp[tid] = s;
    }
    __syncthreads();

    {
        float acc = bd[tid];
#pragma unroll
        for (int h = 0; h < HID_; h++)
            acc = fmaf(xp[h], Wd[h * FC_ + tid], acc);
        hbuf[tid] = fmaxf(acc, 0.f);
    }
    __syncthreads();

    if (tid < C_) {
        float acc = bc[tid];
        for (int f = 0; f < FC_; f++)
            acc = fmaf(hbuf[f], Wc[f * C_ + tid], acc);
        logits[tid] = acc;
    }
    __syncthreads();

    if (tid == 0) {
        float mx = logits[0];
#pragma unroll
        for (int c = 1; c < C_; c++) mx = fmaxf(mx, logits[c]);
        float e[C_];
        float sum = 0.f;
#pragma unroll
        for (int c = 0; c < C_; c++) { e[c] = expf(logits[c] - mx); sum += e[c]; }
        float inv = 1.f / sum;
#pragma unroll
        for (int c = 0; c < C_; c++) out[b * C_ + c] = e[c] * inv;
    }
}

// ---------------------------------------------------------------------------
extern "C" void kernel_launch(void* const* d_in, const int* in_sizes, int n_in,
                              void* d_out, int out_size) {
    const float* filtre = (const float*)d_in[0];
    const float* X      = (const float*)d_in[1];
    // d_in[2] node_indicator: unused by the reference math
    const float* W1     = (const float*)d_in[3];
    const float* b1     = (const float*)d_in[4];
    // d_in[5] Ws: dead (softmax over size-1 cluster axis == 1)
    const float* Wd     = (const float*)d_in[6];
    const float* bd     = (const float*)d_in[7];
    const float* Wc     = (const float*)d_in[8];
    const float* bc     = (const float*)d_in[9];
    float* out = (float*)d_out;

    xw_kernel<<<dim3(N_ / XROWS, B_), 256>>>(X, W1);
    gemm_kernel<<<dim3(MB_, B_), 256>>>(filtre, b1);
    head_kernel<<<B_, FC_>>>(Wd, bd, Wc, bc, out);
}

// round 8
// speedup vs baseline: 3.0952x; 1.2119x over previous
#include <cuda_runtime.h>

#define B_   16
#define N_   2048
#define F_   128
#define HID_ 32
#define FC_  512
#define C_   10

#define BM   128          // rows per block
#define BK   32           // k-tile
#define S_   4            // pipeline stages
#define ASTR 36           // A smem stride (pad)
#define BSTR 40           // B smem stride (pad)
#define MB_  (N_ / BM)    // 16 m-blocks per batch
#define APITCH (BM * ASTR)
#define BPITCH (BK * BSTR)
#define SMEM_BYTES ((S_ * APITCH + S_ * BPITCH) * 4)

// Scratch (no cudaMalloc allowed)
__device__ float g_XW[B_ * N_ * HID_];        // X @ W1  [B,N,HID]
__device__ float g_part[B_ * MB_ * HID_];     // per-block relu column sums

// ---------------- helpers ----------------
__device__ __forceinline__ void cp16(float* dst_smem, const float* src) {
    unsigned s = (unsigned)__cvta_generic_to_shared(dst_smem);
    asm volatile("cp.async.cg.shared.global [%0], [%1], 16;" :: "r"(s), "l"(src));
}
__device__ __forceinline__ void cp_commit() { asm volatile("cp.async.commit_group;"); }
template <int N>
__device__ __forceinline__ void cp_wait() { asm volatile("cp.async.wait_group %0;" :: "n"(N)); }

__device__ __forceinline__ void mma_tf32(float c[4], float a0, float a1, float a2, float a3,
                                         float b0, float b1) {
    asm volatile(
        "mma.sync.aligned.m16n8k8.row.col.f32.tf32.tf32.f32 "
        "{%0,%1,%2,%3}, {%4,%5,%6,%7}, {%8,%9}, {%0,%1,%2,%3};"
        : "+f"(c[0]), "+f"(c[1]), "+f"(c[2]), "+f"(c[3])
        : "r"(__float_as_uint(a0)), "r"(__float_as_uint(a1)),
          "r"(__float_as_uint(a2)), "r"(__float_as_uint(a3)),
          "r"(__float_as_uint(b0)), "r"(__float_as_uint(b1)));
}

// ---------------------------------------------------------------------------
// Unified GEMM: C = A_rows @ B  (N=32), tf32 mma, 4-stage cp.async pipeline.
//   REDUCE=false (xw pass):  A=X (lda=F_), B=Bg=W1, NKT=4; store Y -> g_XW.
//   REDUCE=true  (main):     A=filtre (lda=N_), B=g_XW[b], NKT=64;
//                            relu(Y+b1), column-sum -> g_part[b][mb].
// grid (MB_, B_), 256 threads (8 warps x m16-tile, 4 n8-tiles each).
// ---------------------------------------------------------------------------
template <int NKT, bool REDUCE>
__global__ __launch_bounds__(256) void mm_kernel(const float* __restrict__ A, int lda,
                                                 const float* __restrict__ Bg,
                                                 const float* __restrict__ b1) {
    extern __shared__ __align__(16) float smem[];
    float* As = smem;                       // [S_][BM*ASTR]
    float* Bs = smem + S_ * APITCH;         // [S_][BK*BSTR]
    __shared__ float red[8 * HID_];

    const int tid = threadIdx.x;
    const int b = blockIdx.y;
    const int mb = blockIdx.x;
    const int w = tid >> 5;
    const int lane = tid & 31;
    const int g = lane >> 2;      // group row 0..7
    const int t = lane & 3;       // thread-in-group 0..3

    const float* Ab = A + ((size_t)b * N_ + (size_t)mb * BM) * (size_t)lda;
    const float* Bb = REDUCE ? (g_XW + (size_t)b * N_ * HID_) : Bg;

    float acc[4][4];
#pragma unroll
    for (int nt = 0; nt < 4; nt++)
#pragma unroll
        for (int i = 0; i < 4; i++) acc[nt][i] = 0.f;

    auto stage = [&](int kt, int p) {
        const int k0s = kt * BK;
#pragma unroll
        for (int i = 0; i < 4; i++) {
            int c = tid + i * 256;
            int row = c >> 3, kq = c & 7;
            cp16(&As[p * APITCH + row * ASTR + kq * 4],
                 Ab + (size_t)row * lda + k0s + kq * 4);
        }
        {
            int kk = tid >> 3, j = tid & 7;
            cp16(&Bs[p * BPITCH + kk * BSTR + j * 4],
                 Bb + (size_t)(k0s + kk) * HID_ + j * 4);
        }
    };

    // prologue: S_-1 stages ahead (one commit group each, uniform accounting)
#pragma unroll
    for (int s = 0; s < S_ - 1; s++) {
        if (s < NKT) stage(s, s);
        cp_commit();
    }

    for (int kt = 0; kt < NKT; kt++) {
        const int p = kt & (S_ - 1);
        if (kt + S_ - 1 < NKT) stage(kt + S_ - 1, (kt + S_ - 1) & (S_ - 1));
        cp_commit();                 // always one group per iter (maybe empty)
        cp_wait<S_ - 2>();           // guarantees group for stage kt complete
        __syncthreads();

        const float* Asp = &As[p * APITCH];
        const float* Bsp = &Bs[p * BPITCH];
#pragma unroll
        for (int kc = 0; kc < 4; kc++) {
            const int kb = kc * 8;
            float a0 = Asp[(w * 16 + g)     * ASTR + kb + t];
            float a1 = Asp[(w * 16 + g + 8) * ASTR + kb + t];
            float a2 = Asp[(w * 16 + g)     * ASTR + kb + t + 4];
            float a3 = Asp[(w * 16 + g + 8) * ASTR + kb + t + 4];
#pragma unroll
            for (int nt = 0; nt < 4; nt++) {
                float bb0 = Bsp[(kb + t)     * BSTR + nt * 8 + g];
                float bb1 = Bsp[(kb + t + 4) * BSTR + nt * 8 + g];
                mma_tf32(acc[nt], a0, a1, a2, a3, bb0, bb1);
            }
        }
        __syncthreads();             // protect buffer p before its refill
    }

    if (!REDUCE) {
        // Store Y tile to g_XW. Lane (g,t): rows w*16+g, w*16+g+8; cols nt*8+2t(+1).
        const size_t base = (size_t)b * N_ + (size_t)mb * BM + w * 16;
#pragma unroll
        for (int nt = 0; nt < 4; nt++) {
            float2 v0 = make_float2(acc[nt][0], acc[nt][1]);
            float2 v1 = make_float2(acc[nt][2], acc[nt][3]);
            *reinterpret_cast<float2*>(&g_XW[(base + g)     * HID_ + nt * 8 + 2 * t]) = v0;
            *reinterpret_cast<float2*>(&g_XW[(base + g + 8) * HID_ + nt * 8 + 2 * t]) = v1;
        }
        return;
    }

    // Epilogue: +b1, relu, deterministic column-sum over this block's 128 rows.
    float2 csum[4];
#pragma unroll
    for (int nt = 0; nt < 4; nt++) {
        float2 bb = *reinterpret_cast<const float2*>(b1 + nt * 8 + 2 * t);
        float v0 = fmaxf(acc[nt][0] + bb.x, 0.f) + fmaxf(acc[nt][2] + bb.x, 0.f);
        float v1 = fmaxf(acc[nt][1] + bb.y, 0.f) + fmaxf(acc[nt][3] + bb.y, 0.f);
        csum[nt] = make_float2(v0, v1);
    }
#pragma unroll
    for (int nt = 0; nt < 4; nt++) {
#pragma unroll
        for (int off = 16; off >= 4; off >>= 1) {
            csum[nt].x += __shfl_xor_sync(0xffffffffu, csum[nt].x, off);
            csum[nt].y += __shfl_xor_sync(0xffffffffu, csum[nt].y, off);
        }
    }
    if (g == 0) {
#pragma unroll
        for (int nt = 0; nt < 4; nt++) {
            red[w * HID_ + nt * 8 + 2 * t + 0] = csum[nt].x;
            red[w * HID_ + nt * 8 + 2 * t + 1] = csum[nt].y;
        }
    }
    __syncthreads();
    if (tid < HID_) {
        float s = 0.f;
#pragma unroll
        for (int ww = 0; ww < 8; ww++) s += red[ww * HID_ + tid];
        g_part[((size_t)b * MB_ + mb) * HID_ + tid] = s;
    }
}

// ---------------------------------------------------------------------------
// Head: Xp = sum(partials); h = relu(Xp@Wd+bd); out = softmax(h@Wc+bc)
// ---------------------------------------------------------------------------
__global__ __launch_bounds__(512) void head_kernel(const float* __restrict__ Wd,
                                                   const float* __restrict__ bd,
                                                   const float* __restrict__ Wc,
                                                   const float* __restrict__ bc,
                                                   float* __restrict__ out) {
    __shared__ float xp[HID_];
    __shared__ float hbuf[FC_];
    __shared__ float logits[C_];
    const int b = blockIdx.x;
    const int tid = threadIdx.x;

    if (tid < HID_) {
        float s = 0.f;
#pragma unroll
        for (int mb = 0; mb < MB_; mb++)
            s += g_part[((size_t)b * MB_ + mb) * HID_ + tid];
        xp[tid] = s;
    }
    __syncthreads();

    {
        float acc = bd[tid];
#pragma unroll
        for (int h = 0; h < HID_; h++)
            acc = fmaf(xp[h], Wd[h * FC_ + tid], acc);
        hbuf[tid] = fmaxf(acc, 0.f);
    }
    __syncthreads();

    if (tid < C_) {
        float acc = bc[tid];
        for (int f = 0; f < FC_; f++)
            acc = fmaf(hbuf[f], Wc[f * C_ + tid], acc);
        logits[tid] = acc;
    }
    __syncthreads();

    if (tid == 0) {
        float mx = logits[0];
#pragma unroll
        for (int c = 1; c < C_; c++) mx = fmaxf(mx, logits[c]);
        float e[C_];
        float sum = 0.f;
#pragma unroll
        for (int c = 0; c < C_; c++) { e[c] = expf(logits[c] - mx); sum += e[c]; }
        float inv = 1.f / sum;
#pragma unroll
        for (int c = 0; c < C_; c++) out[b * C_ + c] = e[c] * inv;
    }
}

// ---------------------------------------------------------------------------
extern "C" void kernel_launch(void* const* d_in, const int* in_sizes, int n_in,
                              void* d_out, int out_size) {
    const float* filtre = (const float*)d_in[0];
    const float* X      = (const float*)d_in[1];
    // d_in[2] node_indicator: unused by the reference math
    const float* W1     = (const float*)d_in[3];
    const float* b1     = (const float*)d_in[4];
    // d_in[5] Ws: dead (softmax over size-1 cluster axis == 1)
    const float* Wd     = (const float*)d_in[6];
    const float* bd     = (const float*)d_in[7];
    const float* Wc     = (const float*)d_in[8];
    const float* bc     = (const float*)d_in[9];
    float* out = (float*)d_out;

    // Idempotent, non-stream host calls (not captured; no allocation).
    cudaFuncSetAttribute(mm_kernel<F_ / BK, false>,
                         cudaFuncAttributeMaxDynamicSharedMemorySize, SMEM_BYTES);
    cudaFuncSetAttribute(mm_kernel<N_ / BK, true>,
                         cudaFuncAttributeMaxDynamicSharedMemorySize, SMEM_BYTES);

    mm_kernel<F_ / BK, false><<<dim3(MB_, B_), 256, SMEM_BYTES>>>(X, F_, W1, nullptr);
    mm_kernel<N_ / BK, true ><<<dim3(MB_, B_), 256, SMEM_BYTES>>>(filtre, N_, nullptr, b1);
    head_kernel<<<B_, FC_>>>(Wd, bd, Wc, bc, out);
}